// round 5
// baseline (speedup 1.0000x reference)
#include <cuda_runtime.h>
#include <cuda_bf16.h>
#include <math.h>
#include <stdint.h>

#define BB 8
#define CC 64
#define NN 4096
#define HH 4
#define OO 128
#define KNN 20
#define PP (BB*NN)   // 32768

// ---------------- scratch (device globals; no allocs) ----------------
__device__ float g_pts[(size_t)PP*CC];        // (B,N,C) transposed x
__device__ float g_sq[PP];
__device__ int   g_idx[PP*KNN];
__device__ float g_M[HH*CC*CC];               // Wq^T Wk per head
__device__ float g_Wf[OO*HH*CC];              // Wout folded with Wv
__device__ float g_wd[(size_t)PP*HH*CC];      // weighted difference vectors
__device__ float g_y[(size_t)BB*OO*NN];       // pre-BN output
__device__ float g_mean[OO];
__device__ float g_istd[OO];

// ---------------- K0: transpose x -> pts ----------------
__global__ void k_transpose(const float* __restrict__ x) {
    __shared__ float tile[32][33];
    int b = blockIdx.z;
    int n0 = blockIdx.x * 32, c0 = blockIdx.y * 32;
    for (int i = threadIdx.y; i < 32; i += 8)
        tile[i][threadIdx.x] = x[((size_t)b*CC + c0 + i)*NN + n0 + threadIdx.x];
    __syncthreads();
    for (int i = threadIdx.y; i < 32; i += 8)
        g_pts[((size_t)b*NN + n0 + i)*CC + c0 + threadIdx.x] = tile[threadIdx.x][i];
}

// ---------------- K0b: copy x into out channels [128,192) ----------------
__global__ void k_copyx(const float* __restrict__ x, float* __restrict__ out) {
    size_t i = (size_t)blockIdx.x * blockDim.x + threadIdx.x;
    if (i >= (size_t)BB*CC*NN) return;
    int n = (int)(i & (NN-1));
    size_t t = i >> 12;
    int c = (int)(t & (CC-1));
    int b = (int)(t >> 6);
    out[((size_t)b*192 + 128 + c)*NN + n] = x[i];
}

// ---------------- K1: squared norms ----------------
__global__ void k_sqnorm() {
    int p = blockIdx.x * 8 + (threadIdx.x >> 5);
    int lane = threadIdx.x & 31;
    float v0 = g_pts[(size_t)p*64 + lane];
    float v1 = g_pts[(size_t)p*64 + 32 + lane];
    float s = v0*v0 + v1*v1;
    #pragma unroll
    for (int off = 16; off; off >>= 1) s += __shfl_xor_sync(0xFFFFFFFFu, s, off);
    if (lane == 0) g_sq[p] = s;
}

// ---------------- K2: fused fp32 (f32x2-packed) Gram + streaming top-21 ----------------
// Smem word layout:
//   As:   [0, 8448)       64 k-rows x 132 (128 i + pad) floats
//   Bs:   [8448, 16896)   64 k-rows x 132 (128 j + pad) floats
//   Ds:   [16896, 33792)  128 x 132 floats
//   lval: [33792, 36480)  128*21 floats
//   lidx: [36480, 39168)  128*21 ints
//   sqb:  [39168, 39296)  128 floats
#define KNN_SMEM_BYTES (39296*4)
__global__ void k_knn(const float* __restrict__ x) {
    extern __shared__ float sm[];
    float* As   = sm;
    float* Bs   = sm + 8448;
    float* Ds   = sm + 16896;
    float* lval = sm + 33792;
    int*   lidx = (int*)(sm + 36480);
    float* sqb  = sm + 39168;

    int tid = threadIdx.x;
    int tx = tid & 15, ty = tid >> 4;
    int b = blockIdx.y, it = blockIdx.x;
    const float* xb = x + (size_t)b*CC*NN;

    // load A tile: As[k][i] = x[b][k][it*128 + i]
    {
        int i0 = it*128;
        #pragma unroll
        for (int w = 0; w < 8; w++) {
            int lin = w*1024 + tid*4;
            int k = lin >> 7, i = lin & 127;
            *(float4*)&As[k*132 + i] = *(const float4*)(xb + (size_t)k*NN + i0 + i);
        }
    }

    float si = 0.f, thr = -3.402823466e38f;
    int cnt = 0, LB = tid*21;
    if (tid < 128) si = g_sq[b*4096 + it*128 + tid];

    int aBase = ty*8, bBase = tx*8;

    for (int tj = 0; tj < 32; tj++) {
        // load B tile: Bs[k][j] = x[b][k][tj*128 + j]
        {
            int j0 = tj*128;
            #pragma unroll
            for (int w = 0; w < 8; w++) {
                int lin = w*1024 + tid*4;
                int k = lin >> 7, j = lin & 127;
                *(float4*)&Bs[k*132 + j] = *(const float4*)(xb + (size_t)k*NN + j0 + j);
            }
        }
        if (tid < 128) sqb[tid] = g_sq[b*4096 + tj*128 + tid];
        __syncthreads();   // Bs ready; previous scan finished before Ds overwrite

        // compute 8x8 per thread, j packed in f32x2 pairs
        unsigned long long acc[8][4];
        #pragma unroll
        for (int ii = 0; ii < 8; ii++)
            #pragma unroll
            for (int jp = 0; jp < 4; jp++) acc[ii][jp] = 0ULL;

        #pragma unroll 8
        for (int k = 0; k < 64; k++) {
            float a[8];
            *(float4*)a     = *(float4*)&As[k*132 + aBase];
            *(float4*)(a+4) = *(float4*)&As[k*132 + aBase + 4];
            unsigned long long b2[4];
            #pragma unroll
            for (int jp = 0; jp < 4; jp++)
                b2[jp] = *(const unsigned long long*)&Bs[k*132 + bBase + 2*jp];
            #pragma unroll
            for (int ii = 0; ii < 8; ii++) {
                unsigned long long a2;
                asm("mov.b64 %0, {%1, %1};" : "=l"(a2) : "f"(a[ii]));
                #pragma unroll
                for (int jp = 0; jp < 4; jp++)
                    asm("fma.rn.f32x2 %0, %1, %2, %0;" : "+l"(acc[ii][jp]) : "l"(a2), "l"(b2[jp]));
            }
        }

        // spill D tile
        #pragma unroll
        for (int ii = 0; ii < 8; ii++) {
            int r = aBase + ii;
            #pragma unroll
            for (int jp = 0; jp < 4; jp++) {
                unsigned lo, hi;
                asm("mov.b64 {%0, %1}, %2;" : "=r"(lo), "=r"(hi) : "l"(acc[ii][jp]));
                *(float2*)&Ds[r*132 + bBase + 2*jp] =
                    make_float2(__uint_as_float(lo), __uint_as_float(hi));
            }
        }
        __syncthreads();

        // streaming top-21 scan (threads 0-127, one row each)
        if (tid < 128) {
            const float4* drow = (const float4*)&Ds[tid*132];
            int jb = tj*128;
            #pragma unroll 4
            for (int c4 = 0; c4 < 32; c4++) {
                float4 v4 = drow[c4];
                #pragma unroll
                for (int e = 0; e < 4; e++) {
                    float dot = (e == 0) ? v4.x : (e == 1) ? v4.y : (e == 2) ? v4.z : v4.w;
                    int j = c4*4 + e;
                    float d = 2.f*dot - si - sqb[j];
                    if (d > thr) {
                        int pos = (cnt < 21) ? cnt++ : 20;
                        while (pos > 0 && lval[LB + pos - 1] < d) {
                            lval[LB + pos] = lval[LB + pos - 1];
                            lidx[LB + pos] = lidx[LB + pos - 1];
                            pos--;
                        }
                        lval[LB + pos] = d;
                        lidx[LB + pos] = jb + j;
                        if (cnt == 21) thr = lval[LB + 20];
                    }
                }
            }
        }
        __syncthreads();
    }

    if (tid < 128) {
        int p = b*4096 + it*128 + tid;
        #pragma unroll
        for (int k = 0; k < 20; k++) g_idx[p*20 + k] = lidx[LB + 1 + k];
    }
}

// ---------------- K3: precompute M = Wq^T Wk per head ----------------
__global__ void k_precM(const float* __restrict__ Wq, const float* __restrict__ Wk) {
    int id = blockIdx.x * 256 + threadIdx.x;
    int cp = id & 63;
    int c  = (id >> 6) & 63;
    int h  = id >> 12;
    float acc = 0.f;
    #pragma unroll 8
    for (int e = 0; e < 64; e++)
        acc += Wq[(h*64 + e)*64 + c] * Wk[(h*64 + e)*64 + cp];
    g_M[id] = acc;
}

// ---------------- K3b: precompute Wf = Wout folded with Wv ----------------
__global__ void k_precWf(const float* __restrict__ Wout, const float* __restrict__ Wv) {
    int id = blockIdx.x * 256 + threadIdx.x;
    int c = id & 63;
    int h = (id >> 6) & 3;
    int o = id >> 8;
    float acc = 0.f;
    #pragma unroll 8
    for (int v = 0; v < 64; v++)
        acc += Wout[o*256 + h*64 + v] * Wv[(h*64 + v)*64 + c];
    g_Wf[id] = acc;
}

// ---------------- K5: per-point attention -> weighted difference vectors ----------------
#define WPB 8
__global__ void k_attn() {
    __shared__ float nb[WPB][KNN][64];
    __shared__ float qs[WPB][64];
    __shared__ float tq[WPB][64];
    __shared__ float ps[WPB][KNN];
    __shared__ int   nbi[WPB][KNN];

    int w = threadIdx.x >> 5;
    int lane = threadIdx.x & 31;
    int p = blockIdx.x * WPB + w;
    int b = p >> 12;

    if (lane < KNN) nbi[w][lane] = g_idx[p * KNN + lane];
    float q0 = g_pts[(size_t)p*64 + lane];
    float q1 = g_pts[(size_t)p*64 + 32 + lane];
    qs[w][lane] = q0;
    qs[w][lane + 32] = q1;
    __syncwarp();
    #pragma unroll 4
    for (int k = 0; k < KNN; k++) {
        int j = nbi[w][k];
        const float* src = g_pts + ((size_t)(b << 12) + j)*64;
        nb[w][k][lane]      = src[lane];
        nb[w][k][lane + 32] = src[lane + 32];
    }
    __syncwarp();

    for (int h = 0; h < HH; h++) {
        const float* Mh = g_M + h * 4096;
        float t0 = 0.f, t1 = 0.f;
        #pragma unroll 8
        for (int c = 0; c < 64; c++) {
            float qc = qs[w][c];
            t0 += qc * __ldg(Mh + c*64 + lane);
            t1 += qc * __ldg(Mh + c*64 + 32 + lane);
        }
        tq[w][lane] = t0;
        tq[w][lane + 32] = t1;
        __syncwarp();

        float s = -3.402823466e38f;
        if (lane < KNN) {
            float acc = 0.f;
            #pragma unroll 8
            for (int c = 0; c < 64; c++) acc += tq[w][c] * nb[w][lane][c];
            s = acc * 0.125f;
        }
        float mx = s;
        #pragma unroll
        for (int off = 16; off; off >>= 1) mx = fmaxf(mx, __shfl_xor_sync(0xFFFFFFFFu, mx, off));
        float e = (lane < KNN) ? expf(s - mx) : 0.f;
        float sum = e;
        #pragma unroll
        for (int off = 16; off; off >>= 1) sum += __shfl_xor_sync(0xFFFFFFFFu, sum, off);
        if (lane < KNN) ps[w][lane] = e / sum;
        __syncwarp();

        float w0 = 0.f, w1 = 0.f;
        #pragma unroll 4
        for (int k = 0; k < KNN; k++) {
            float pk = ps[w][k];
            w0 += pk * (nb[w][k][lane]      - q0);
            w1 += pk * (nb[w][k][lane + 32] - q1);
        }
        g_wd[((size_t)p*HH + h)*64 + lane]      = w0;
        g_wd[((size_t)p*HH + h)*64 + 32 + lane] = w1;
        __syncwarp();
    }
}

// ---------------- K6: y = Wf (128x256) @ wd^T ----------------
__global__ void k_ygemm() {
    __shared__ float Wfs[32][129];
    __shared__ float wds[64][33];
    int tid = threadIdx.y * 16 + threadIdx.x;
    int p0 = blockIdx.x * 64;
    float acc[8][4] = {};

    for (int kt = 0; kt < 8; kt++) {
        for (int t = tid; t < 4096; t += 256) {
            int o = t >> 5, k = t & 31;
            Wfs[k][o] = g_Wf[o*256 + kt*32 + k];
        }
        for (int t = tid; t < 2048; t += 256) {
            int pp = t >> 5, k = t & 31;
            wds[pp][k] = g_wd[(size_t)(p0 + pp)*256 + kt*32 + k];
        }
        __syncthreads();
        #pragma unroll 8
        for (int k = 0; k < 32; k++) {
            float a[8], bb[4];
            #pragma unroll
            for (int ii = 0; ii < 8; ii++) a[ii] = Wfs[k][threadIdx.y*8 + ii];
            #pragma unroll
            for (int jj = 0; jj < 4; jj++) bb[jj] = wds[threadIdx.x*4 + jj][k];
            #pragma unroll
            for (int ii = 0; ii < 8; ii++)
                #pragma unroll
                for (int jj = 0; jj < 4; jj++)
                    acc[ii][jj] += a[ii] * bb[jj];
        }
        __syncthreads();
    }
    #pragma unroll
    for (int ii = 0; ii < 8; ii++) {
        int o = threadIdx.y*8 + ii;
        #pragma unroll
        for (int jj = 0; jj < 4; jj++) {
            int p = p0 + threadIdx.x*4 + jj;
            g_y[((size_t)(p >> 12)*OO + o)*NN + (p & 4095)] = acc[ii][jj];
        }
    }
}

// ---------------- K7: BN stats (double accumulation) ----------------
__global__ void k_bnstats() {
    __shared__ double rs[256], rss[256];
    int o = blockIdx.x;
    int tid = threadIdx.x;
    double s = 0.0, ss = 0.0;
    for (int b = 0; b < BB; b++) {
        const float* row = g_y + ((size_t)b*OO + o)*NN;
        for (int t = tid; t < NN; t += 256) {
            double v = (double)row[t];
            s += v; ss += v*v;
        }
    }
    rs[tid] = s; rss[tid] = ss;
    __syncthreads();
    for (int st = 128; st; st >>= 1) {
        if (tid < st) { rs[tid] += rs[tid + st]; rss[tid] += rss[tid + st]; }
        __syncthreads();
    }
    if (tid == 0) {
        double n = (double)(BB*NN);
        double mean = rs[0] / n;
        double var = rss[0] / n - mean*mean;
        g_mean[o] = (float)mean;
        g_istd[o] = (float)(1.0 / sqrt(var + 1e-5));
    }
}

// ---------------- K8: BN apply + LeakyReLU -> out channels [0,128) ----------------
__global__ void k_bnapply(const float* __restrict__ gamma, const float* __restrict__ beta,
                          float* __restrict__ out) {
    size_t i = (size_t)blockIdx.x * blockDim.x + threadIdx.x;
    if (i >= (size_t)BB*OO*NN) return;
    int n = (int)(i & (NN-1));
    size_t t = i >> 12;
    int o = (int)(t & (OO-1));
    int b = (int)(t >> 7);
    float v = (g_y[i] - g_mean[o]) * g_istd[o] * gamma[o] + beta[o];
    v = (v >= 0.f) ? v : 0.2f * v;
    out[((size_t)b*192 + o)*NN + n] = v;
}

// ---------------- launch ----------------
extern "C" void kernel_launch(void* const* d_in, const int* in_sizes, int n_in,
                              void* d_out, int out_size) {
    const float* x     = (const float*)d_in[0];
    const float* Wq    = (const float*)d_in[1];
    const float* Wk    = (const float*)d_in[2];
    const float* Wv    = (const float*)d_in[3];
    const float* Wout  = (const float*)d_in[4];
    const float* gamma = (const float*)d_in[5];
    const float* beta  = (const float*)d_in[6];
    float* out = (float*)d_out;

    cudaFuncSetAttribute(k_knn, cudaFuncAttributeMaxDynamicSharedMemorySize, KNN_SMEM_BYTES);

    k_transpose<<<dim3(NN/32, CC/32, BB), dim3(32, 8)>>>(x);
    k_copyx<<<(BB*CC*NN)/256, 256>>>(x, out);
    k_sqnorm<<<PP/8, 256>>>();
    k_knn<<<dim3(32, 8), 256, KNN_SMEM_BYTES>>>(x);       // 4th launch -> gets profiled
    k_precM<<<64, 256>>>(Wq, Wk);
    k_precWf<<<128, 256>>>(Wout, Wv);
    k_attn<<<PP/WPB, 256>>>();
    k_ygemm<<<PP/64, dim3(16, 16)>>>();
    k_bnstats<<<OO, 256>>>();
    k_bnapply<<<(BB*OO*NN)/256, 256>>>(gamma, beta, out);
}

// round 6
// speedup vs baseline: 1.2380x; 1.2380x over previous
#include <cuda_runtime.h>
#include <cuda_bf16.h>
#include <math.h>
#include <stdint.h>

#define BB 8
#define CC 64
#define NN 4096
#define HH 4
#define OO 128
#define KNN 20
#define PP (BB*NN)   // 32768

// ---------------- scratch (device globals; no allocs) ----------------
__device__ float g_pdist[(size_t)BB*NN*NN];   // 536 MB
__device__ float g_pts[(size_t)PP*CC];        // (B,N,C) transposed x
__device__ int   g_idx[PP*KNN];
__device__ float g_M[HH*CC*CC];               // Wq^T Wk per head
__device__ float g_Wf[OO*HH*CC];              // Wout folded with Wv
__device__ float g_wd[(size_t)PP*HH*CC];      // weighted difference vectors
__device__ float g_y[(size_t)BB*OO*NN];       // pre-BN output
__device__ float g_mean[OO];
__device__ float g_istd[OO];

// ---------------- K0: transpose x -> pts (for attn gather) ----------------
__global__ void k_transpose(const float* __restrict__ x) {
    __shared__ float tile[32][33];
    int b = blockIdx.z;
    int n0 = blockIdx.x * 32, c0 = blockIdx.y * 32;
    for (int i = threadIdx.y; i < 32; i += 8)
        tile[i][threadIdx.x] = x[((size_t)b*CC + c0 + i)*NN + n0 + threadIdx.x];
    __syncthreads();
    for (int i = threadIdx.y; i < 32; i += 8)
        g_pts[((size_t)b*NN + n0 + i)*CC + c0 + threadIdx.x] = tile[threadIdx.x][i];
}

// ---------------- K0b: copy x into out channels [128,192) ----------------
__global__ void k_copyx(const float* __restrict__ x, float* __restrict__ out) {
    size_t i = (size_t)blockIdx.x * blockDim.x + threadIdx.x;
    if (i >= (size_t)BB*CC*NN) return;
    int n = (int)(i & (NN-1));
    size_t t = i >> 12;
    int c = (int)(t & (CC-1));
    int b = (int)(t >> 6);
    out[((size_t)b*192 + 128 + c)*NN + n] = x[i];
}

// ---------------- K1: precompute Wf = Wout folded with Wv ----------------
__global__ void k_precWf(const float* __restrict__ Wout, const float* __restrict__ Wv) {
    int id = blockIdx.x * 256 + threadIdx.x;
    int c = id & 63;
    int h = (id >> 6) & 3;
    int o = id >> 8;
    float acc = 0.f;
    #pragma unroll 8
    for (int v = 0; v < 64; v++)
        acc += Wout[o*256 + h*64 + v] * Wv[(h*64 + v)*64 + c];
    g_Wf[id] = acc;
}

// ---------------- K2: pdist = 2*dot - si - sj  (f32x2 packed, 128x128 tiles) ----------------
// smem floats: As [0,8448) 64x132 (c,i), Bs [8448,16896) 64x132 (c,j),
//              sqa [16896,17024), sqb [17024,17152)
#define PD_SMEM_BYTES (17152*4)
__global__ void k_pdist(const float* __restrict__ x) {
    extern __shared__ float sm[];
    float* As  = sm;
    float* Bs  = sm + 8448;
    float* sqa = sm + 16896;
    float* sqb = sm + 17024;

    int tid = threadIdx.x;
    int tx = tid & 15, ty = tid >> 4;
    int b = blockIdx.z, it = blockIdx.y, jt = blockIdx.x;
    const float* xb = x + (size_t)b*CC*NN;

    // load A tile: As[c][i] = x[b][c][it*128+i]; B tile similarly
    {
        int i0 = it*128, j0 = jt*128;
        #pragma unroll
        for (int w = 0; w < 8; w++) {
            int lin = w*1024 + tid*4;
            int c = lin >> 7, i = lin & 127;
            *(float4*)&As[c*132 + i] = *(const float4*)(xb + (size_t)c*NN + i0 + i);
            *(float4*)&Bs[c*132 + i] = *(const float4*)(xb + (size_t)c*NN + j0 + i);
        }
    }
    __syncthreads();

    // squared norms from tiles
    if (tid < 128) {
        float s = 0.f;
        #pragma unroll 8
        for (int c = 0; c < 64; c++) { float v = As[c*132 + tid]; s += v*v; }
        sqa[tid] = s;
    } else {
        int t = tid - 128;
        float s = 0.f;
        #pragma unroll 8
        for (int c = 0; c < 64; c++) { float v = Bs[c*132 + t]; s += v*v; }
        sqb[t] = s;
    }
    __syncthreads();

    int aBase = ty*8, bBase = tx*8;

    unsigned long long acc[8][4];
    #pragma unroll
    for (int ii = 0; ii < 8; ii++)
        #pragma unroll
        for (int jp = 0; jp < 4; jp++) acc[ii][jp] = 0ULL;

    #pragma unroll 8
    for (int c = 0; c < 64; c++) {
        float a[8];
        *(float4*)a     = *(float4*)&As[c*132 + aBase];
        *(float4*)(a+4) = *(float4*)&As[c*132 + aBase + 4];
        unsigned long long b2[4];
        #pragma unroll
        for (int jp = 0; jp < 4; jp++)
            b2[jp] = *(const unsigned long long*)&Bs[c*132 + bBase + 2*jp];
        #pragma unroll
        for (int ii = 0; ii < 8; ii++) {
            unsigned long long a2;
            asm("mov.b64 %0, {%1, %1};" : "=l"(a2) : "f"(a[ii]));
            #pragma unroll
            for (int jp = 0; jp < 4; jp++)
                asm("fma.rn.f32x2 %0, %1, %2, %0;" : "+l"(acc[ii][jp]) : "l"(a2), "l"(b2[jp]));
        }
    }

    // epilogue: d = 2*dot - si - sj, store
    #pragma unroll
    for (int ii = 0; ii < 8; ii++) {
        int r = aBase + ii;
        float sr = sqa[r];
        float o[8];
        #pragma unroll
        for (int jp = 0; jp < 4; jp++) {
            unsigned lo, hi;
            asm("mov.b64 {%0, %1}, %2;" : "=r"(lo), "=r"(hi) : "l"(acc[ii][jp]));
            o[2*jp]   = 2.f*__uint_as_float(lo) - sr - sqb[bBase + 2*jp];
            o[2*jp+1] = 2.f*__uint_as_float(hi) - sr - sqb[bBase + 2*jp + 1];
        }
        size_t g = ((size_t)(b*4096 + it*128 + r))*4096 + jt*128 + bBase;
        *(float4*)&g_pdist[g]     = make_float4(o[0], o[1], o[2], o[3]);
        *(float4*)&g_pdist[g + 4] = make_float4(o[4], o[5], o[6], o[7]);
    }
}

// ---------------- K3: single-pass streaming top-21 ----------------
// 256 blocks x 256 threads; block handles 128 rows; columns staged 32 at a time.
__global__ void k_topk() {
    __shared__ float tile[128*33];
    __shared__ float lval[128*21];
    __shared__ int   lidx[128*21];

    int tid = threadIdx.x;
    size_t base = (size_t)blockIdx.x * 128 * 4096;

    float thr = -3.402823466e38f;
    int cnt = 0;
    int LB = (tid < 128) ? tid*21 : 0;

    for (int ch = 0; ch < 128; ch++) {
        // stage 128 rows x 32 cols (coalesced)
        #pragma unroll
        for (int i = 0; i < 16; i++) {
            int lin = i*256 + tid;
            int r = lin >> 5, c = lin & 31;
            tile[r*33 + c] = g_pdist[base + (size_t)r*4096 + ch*32 + c];
        }
        __syncthreads();

        if (tid < 128) {
            int jb = ch*32;
            #pragma unroll 4
            for (int c = 0; c < 32; c++) {
                float d = tile[tid*33 + c];
                if (d > thr) {
                    int pos = (cnt < 21) ? cnt++ : 20;
                    while (pos > 0 && lval[LB + pos - 1] < d) {
                        lval[LB + pos] = lval[LB + pos - 1];
                        lidx[LB + pos] = lidx[LB + pos - 1];
                        pos--;
                    }
                    lval[LB + pos] = d;
                    lidx[LB + pos] = jb + c;
                    if (cnt == 21) thr = lval[LB + 20];
                }
            }
        }
        __syncthreads();
    }

    if (tid < 128) {
        int p = blockIdx.x*128 + tid;
        #pragma unroll
        for (int k = 0; k < 20; k++) g_idx[p*20 + k] = lidx[LB + 1 + k];
    }
}

// ---------------- K4: precompute M = Wq^T Wk per head ----------------
__global__ void k_precM(const float* __restrict__ Wq, const float* __restrict__ Wk) {
    int id = blockIdx.x * 256 + threadIdx.x;
    int cp = id & 63;
    int c  = (id >> 6) & 63;
    int h  = id >> 12;
    float acc = 0.f;
    #pragma unroll 8
    for (int e = 0; e < 64; e++)
        acc += Wq[(h*64 + e)*64 + c] * Wk[(h*64 + e)*64 + cp];
    g_M[id] = acc;
}

// ---------------- K5: per-point attention -> weighted difference vectors ----------------
#define WPB 8
__global__ void k_attn() {
    __shared__ float nb[WPB][KNN][64];
    __shared__ float qs[WPB][64];
    __shared__ float tq[WPB][64];
    __shared__ float ps[WPB][KNN];
    __shared__ int   nbi[WPB][KNN];

    int w = threadIdx.x >> 5;
    int lane = threadIdx.x & 31;
    int p = blockIdx.x * WPB + w;
    int b = p >> 12;

    if (lane < KNN) nbi[w][lane] = g_idx[p * KNN + lane];
    float q0 = g_pts[(size_t)p*64 + lane];
    float q1 = g_pts[(size_t)p*64 + 32 + lane];
    qs[w][lane] = q0;
    qs[w][lane + 32] = q1;
    __syncwarp();
    #pragma unroll 4
    for (int k = 0; k < KNN; k++) {
        int j = nbi[w][k];
        const float* src = g_pts + ((size_t)(b << 12) + j)*64;
        nb[w][k][lane]      = src[lane];
        nb[w][k][lane + 32] = src[lane + 32];
    }
    __syncwarp();

    for (int h = 0; h < HH; h++) {
        const float* Mh = g_M + h * 4096;
        float t0 = 0.f, t1 = 0.f;
        #pragma unroll 8
        for (int c = 0; c < 64; c++) {
            float qc = qs[w][c];
            t0 += qc * __ldg(Mh + c*64 + lane);
            t1 += qc * __ldg(Mh + c*64 + 32 + lane);
        }
        tq[w][lane] = t0;
        tq[w][lane + 32] = t1;
        __syncwarp();

        float s = -3.402823466e38f;
        if (lane < KNN) {
            float acc = 0.f;
            #pragma unroll 8
            for (int c = 0; c < 64; c++) acc += tq[w][c] * nb[w][lane][c];
            s = acc * 0.125f;
        }
        float mx = s;
        #pragma unroll
        for (int off = 16; off; off >>= 1) mx = fmaxf(mx, __shfl_xor_sync(0xFFFFFFFFu, mx, off));
        float e = (lane < KNN) ? expf(s - mx) : 0.f;
        float sum = e;
        #pragma unroll
        for (int off = 16; off; off >>= 1) sum += __shfl_xor_sync(0xFFFFFFFFu, sum, off);
        if (lane < KNN) ps[w][lane] = e / sum;
        __syncwarp();

        float w0 = 0.f, w1 = 0.f;
        #pragma unroll 4
        for (int k = 0; k < KNN; k++) {
            float pk = ps[w][k];
            w0 += pk * (nb[w][k][lane]      - q0);
            w1 += pk * (nb[w][k][lane + 32] - q1);
        }
        g_wd[((size_t)p*HH + h)*64 + lane]      = w0;
        g_wd[((size_t)p*HH + h)*64 + 32 + lane] = w1;
        __syncwarp();
    }
}

// ---------------- K6: y = Wf (128x256) @ wd^T ----------------
__global__ void k_ygemm() {
    __shared__ float Wfs[32][129];
    __shared__ float wds[64][33];
    int tid = threadIdx.y * 16 + threadIdx.x;
    int p0 = blockIdx.x * 64;
    float acc[8][4] = {};

    for (int kt = 0; kt < 8; kt++) {
        for (int t = tid; t < 4096; t += 256) {
            int o = t >> 5, k = t & 31;
            Wfs[k][o] = g_Wf[o*256 + kt*32 + k];
        }
        for (int t = tid; t < 2048; t += 256) {
            int pp = t >> 5, k = t & 31;
            wds[pp][k] = g_wd[(size_t)(p0 + pp)*256 + kt*32 + k];
        }
        __syncthreads();
        #pragma unroll 8
        for (int k = 0; k < 32; k++) {
            float a[8], bb[4];
            #pragma unroll
            for (int ii = 0; ii < 8; ii++) a[ii] = Wfs[k][threadIdx.y*8 + ii];
            #pragma unroll
            for (int jj = 0; jj < 4; jj++) bb[jj] = wds[threadIdx.x*4 + jj][k];
            #pragma unroll
            for (int ii = 0; ii < 8; ii++)
                #pragma unroll
                for (int jj = 0; jj < 4; jj++)
                    acc[ii][jj] += a[ii] * bb[jj];
        }
        __syncthreads();
    }
    #pragma unroll
    for (int ii = 0; ii < 8; ii++) {
        int o = threadIdx.y*8 + ii;
        #pragma unroll
        for (int jj = 0; jj < 4; jj++) {
            int p = p0 + threadIdx.x*4 + jj;
            g_y[((size_t)(p >> 12)*OO + o)*NN + (p & 4095)] = acc[ii][jj];
        }
    }
}

// ---------------- K7: BN stats (double accumulation) ----------------
__global__ void k_bnstats() {
    __shared__ double rs[256], rss[256];
    int o = blockIdx.x;
    int tid = threadIdx.x;
    double s = 0.0, ss = 0.0;
    for (int b = 0; b < BB; b++) {
        const float* row = g_y + ((size_t)b*OO + o)*NN;
        for (int t = tid; t < NN; t += 256) {
            double v = (double)row[t];
            s += v; ss += v*v;
        }
    }
    rs[tid] = s; rss[tid] = ss;
    __syncthreads();
    for (int st = 128; st; st >>= 1) {
        if (tid < st) { rs[tid] += rs[tid + st]; rss[tid] += rss[tid + st]; }
        __syncthreads();
    }
    if (tid == 0) {
        double n = (double)(BB*NN);
        double mean = rs[0] / n;
        double var = rss[0] / n - mean*mean;
        g_mean[o] = (float)mean;
        g_istd[o] = (float)(1.0 / sqrt(var + 1e-5));
    }
}

// ---------------- K8: BN apply + LeakyReLU -> out channels [0,128) ----------------
__global__ void k_bnapply(const float* __restrict__ gamma, const float* __restrict__ beta,
                          float* __restrict__ out) {
    size_t i = (size_t)blockIdx.x * blockDim.x + threadIdx.x;
    if (i >= (size_t)BB*OO*NN) return;
    int n = (int)(i & (NN-1));
    size_t t = i >> 12;
    int o = (int)(t & (OO-1));
    int b = (int)(t >> 7);
    float v = (g_y[i] - g_mean[o]) * g_istd[o] * gamma[o] + beta[o];
    v = (v >= 0.f) ? v : 0.2f * v;
    out[((size_t)b*192 + o)*NN + n] = v;
}

// ---------------- launch ----------------
extern "C" void kernel_launch(void* const* d_in, const int* in_sizes, int n_in,
                              void* d_out, int out_size) {
    const float* x     = (const float*)d_in[0];
    const float* Wq    = (const float*)d_in[1];
    const float* Wk    = (const float*)d_in[2];
    const float* Wv    = (const float*)d_in[3];
    const float* Wout  = (const float*)d_in[4];
    const float* gamma = (const float*)d_in[5];
    const float* beta  = (const float*)d_in[6];
    float* out = (float*)d_out;

    cudaFuncSetAttribute(k_pdist, cudaFuncAttributeMaxDynamicSharedMemorySize, PD_SMEM_BYTES);

    k_transpose<<<dim3(NN/32, CC/32, BB), dim3(32, 8)>>>(x);
    k_copyx<<<(BB*CC*NN)/256, 256>>>(x, out);
    k_precWf<<<128, 256>>>(Wout, Wv);
    k_pdist<<<dim3(32, 32, BB), 256, PD_SMEM_BYTES>>>(x);   // 4th launch -> profiled
    k_topk<<<256, 256>>>();
    k_precM<<<64, 256>>>(Wq, Wk);
    k_attn<<<PP/WPB, 256>>>();
    k_ygemm<<<PP/64, dim3(16, 16)>>>();
    k_bnstats<<<OO, 256>>>();
    k_bnapply<<<(BB*OO*NN)/256, 256>>>(gamma, beta, out);
}

// round 7
// speedup vs baseline: 1.4481x; 1.1697x over previous
#include <cuda_runtime.h>
#include <cuda_bf16.h>
#include <math.h>
#include <stdint.h>

#define BB 8
#define CC 64
#define NN 4096
#define HH 4
#define OO 128
#define KNN 20
#define PP (BB*NN)   // 32768

// ---------------- scratch (device globals; no allocs) ----------------
__device__ float g_pdist[(size_t)BB*NN*NN];   // 536 MB
__device__ float g_pts[(size_t)PP*CC];        // (B,N,C) transposed x
__device__ int   g_idx[PP*KNN];
__device__ float g_M[HH*CC*CC];               // Wq^T Wk per head
__device__ float g_tq[(size_t)PP*256];        // q @ M, per point per head
__device__ float g_Wf[OO*HH*CC];              // Wout folded with Wv
__device__ float g_wd[(size_t)PP*HH*CC];      // weighted difference vectors
__device__ float g_y[(size_t)BB*OO*NN];       // pre-BN output
__device__ float g_mean[OO];
__device__ float g_istd[OO];

// ---------------- K: transpose x -> pts (for attn gather / qt) ----------------
__global__ void k_transpose(const float* __restrict__ x) {
    __shared__ float tile[32][33];
    int b = blockIdx.z;
    int n0 = blockIdx.x * 32, c0 = blockIdx.y * 32;
    for (int i = threadIdx.y; i < 32; i += 8)
        tile[i][threadIdx.x] = x[((size_t)b*CC + c0 + i)*NN + n0 + threadIdx.x];
    __syncthreads();
    for (int i = threadIdx.y; i < 32; i += 8)
        g_pts[((size_t)b*NN + n0 + i)*CC + c0 + threadIdx.x] = tile[threadIdx.x][i];
}

// ---------------- K: copy x into out channels [128,192) ----------------
__global__ void k_copyx(const float* __restrict__ x, float* __restrict__ out) {
    size_t i = (size_t)blockIdx.x * blockDim.x + threadIdx.x;
    if (i >= (size_t)BB*CC*NN) return;
    int n = (int)(i & (NN-1));
    size_t t = i >> 12;
    int c = (int)(t & (CC-1));
    int b = (int)(t >> 6);
    out[((size_t)b*192 + 128 + c)*NN + n] = x[i];
}

// ---------------- K: precompute Wf = Wout folded with Wv ----------------
__global__ void k_precWf(const float* __restrict__ Wout, const float* __restrict__ Wv) {
    int id = blockIdx.x * 256 + threadIdx.x;
    int c = id & 63;
    int h = (id >> 6) & 3;
    int o = id >> 8;
    float acc = 0.f;
    #pragma unroll 8
    for (int v = 0; v < 64; v++)
        acc += Wout[o*256 + h*64 + v] * Wv[(h*64 + v)*64 + c];
    g_Wf[id] = acc;
}

// ---------------- K: pdist = 2*dot - si - sj  (f32x2 packed, 128x128 tiles) ----------------
#define PD_SMEM_BYTES (17152*4)
__global__ void k_pdist(const float* __restrict__ x) {
    extern __shared__ float sm[];
    float* As  = sm;
    float* Bs  = sm + 8448;
    float* sqa = sm + 16896;
    float* sqb = sm + 17024;

    int tid = threadIdx.x;
    int tx = tid & 15, ty = tid >> 4;
    int b = blockIdx.z, it = blockIdx.y, jt = blockIdx.x;
    const float* xb = x + (size_t)b*CC*NN;

    {
        int i0 = it*128, j0 = jt*128;
        #pragma unroll
        for (int w = 0; w < 8; w++) {
            int lin = w*1024 + tid*4;
            int c = lin >> 7, i = lin & 127;
            *(float4*)&As[c*132 + i] = *(const float4*)(xb + (size_t)c*NN + i0 + i);
            *(float4*)&Bs[c*132 + i] = *(const float4*)(xb + (size_t)c*NN + j0 + i);
        }
    }
    __syncthreads();

    if (tid < 128) {
        float s = 0.f;
        #pragma unroll 8
        for (int c = 0; c < 64; c++) { float v = As[c*132 + tid]; s += v*v; }
        sqa[tid] = s;
    } else {
        int t = tid - 128;
        float s = 0.f;
        #pragma unroll 8
        for (int c = 0; c < 64; c++) { float v = Bs[c*132 + t]; s += v*v; }
        sqb[t] = s;
    }
    __syncthreads();

    int aBase = ty*8, bBase = tx*8;

    unsigned long long acc[8][4];
    #pragma unroll
    for (int ii = 0; ii < 8; ii++)
        #pragma unroll
        for (int jp = 0; jp < 4; jp++) acc[ii][jp] = 0ULL;

    #pragma unroll 8
    for (int c = 0; c < 64; c++) {
        float a[8];
        *(float4*)a     = *(float4*)&As[c*132 + aBase];
        *(float4*)(a+4) = *(float4*)&As[c*132 + aBase + 4];
        unsigned long long b2[4];
        #pragma unroll
        for (int jp = 0; jp < 4; jp++)
            b2[jp] = *(const unsigned long long*)&Bs[c*132 + bBase + 2*jp];
        #pragma unroll
        for (int ii = 0; ii < 8; ii++) {
            unsigned long long a2;
            asm("mov.b64 %0, {%1, %1};" : "=l"(a2) : "f"(a[ii]));
            #pragma unroll
            for (int jp = 0; jp < 4; jp++)
                asm("fma.rn.f32x2 %0, %1, %2, %0;" : "+l"(acc[ii][jp]) : "l"(a2), "l"(b2[jp]));
        }
    }

    #pragma unroll
    for (int ii = 0; ii < 8; ii++) {
        int r = aBase + ii;
        float sr = sqa[r];
        float o[8];
        #pragma unroll
        for (int jp = 0; jp < 4; jp++) {
            unsigned lo, hi;
            asm("mov.b64 {%0, %1}, %2;" : "=r"(lo), "=r"(hi) : "l"(acc[ii][jp]));
            o[2*jp]   = 2.f*__uint_as_float(lo) - sr - sqb[bBase + 2*jp];
            o[2*jp+1] = 2.f*__uint_as_float(hi) - sr - sqb[bBase + 2*jp + 1];
        }
        size_t g = ((size_t)(b*4096 + it*128 + r))*4096 + jt*128 + bBase;
        *(float4*)&g_pdist[g]     = make_float4(o[0], o[1], o[2], o[3]);
        *(float4*)&g_pdist[g + 4] = make_float4(o[4], o[5], o[6], o[7]);
    }
}

// ---------------- K: single-pass streaming top-21 (prefetch-pipelined) ----------------
__global__ void k_topk() {
    __shared__ float tile[128*33];
    __shared__ float lval[128*21];
    __shared__ int   lidx[128*21];

    int tid = threadIdx.x;
    int rr = tid >> 5, cc0 = tid & 31;
    size_t base = (size_t)blockIdx.x * 128 * 4096;

    float thr = -3.402823466e38f;
    int cnt = 0;
    int LB = (tid < 128) ? tid*21 : 0;

    float pre[16];
    #pragma unroll
    for (int i = 0; i < 16; i++)
        pre[i] = g_pdist[base + (size_t)(i*8 + rr)*4096 + cc0];

    for (int ch = 0; ch < 128; ch++) {
        #pragma unroll
        for (int i = 0; i < 16; i++)
            tile[(i*8 + rr)*33 + cc0] = pre[i];
        __syncthreads();

        if (ch < 127) {
            size_t nb = base + (size_t)(ch + 1)*32 + cc0;
            #pragma unroll
            for (int i = 0; i < 16; i++)
                pre[i] = g_pdist[nb + (size_t)(i*8 + rr)*4096];
        }

        if (tid < 128) {
            int jb = ch*32;
            #pragma unroll 4
            for (int c = 0; c < 32; c++) {
                float d = tile[tid*33 + c];
                if (d > thr) {
                    int pos = (cnt < 21) ? cnt++ : 20;
                    while (pos > 0 && lval[LB + pos - 1] < d) {
                        lval[LB + pos] = lval[LB + pos - 1];
                        lidx[LB + pos] = lidx[LB + pos - 1];
                        pos--;
                    }
                    lval[LB + pos] = d;
                    lidx[LB + pos] = jb + c;
                    if (cnt == 21) thr = lval[LB + 20];
                }
            }
        }
        __syncthreads();
    }

    if (tid < 128) {
        int p = blockIdx.x*128 + tid;
        #pragma unroll
        for (int k = 0; k < 20; k++) g_idx[p*20 + k] = lidx[LB + 1 + k];
    }
}

// ---------------- K: precompute M = Wq^T Wk per head ----------------
__global__ void k_precM(const float* __restrict__ Wq, const float* __restrict__ Wk) {
    int id = blockIdx.x * 256 + threadIdx.x;
    int cp = id & 63;
    int c  = (id >> 6) & 63;
    int h  = id >> 12;
    float acc = 0.f;
    #pragma unroll 8
    for (int e = 0; e < 64; e++)
        acc += Wq[(h*64 + e)*64 + c] * Wk[(h*64 + e)*64 + cp];
    g_M[id] = acc;
}

// ---------------- K: tq = pts @ M  (all points, all heads) ----------------
// grid (PP/64, 2), block (16,16). Block: 64 points x 128 eprime.
__global__ void k_qt() {
    __shared__ float Ms[32][132];
    __shared__ float Qs[64][33];
    int tx = threadIdx.x, ty = threadIdx.y;
    int tid = ty*16 + tx;
    int p0 = blockIdx.x * 64;
    int eb = blockIdx.y * 128;

    float acc[4][8] = {};

    for (int kt = 0; kt < 2; kt++) {
        for (int t = tid; t < 4096; t += 256) {
            int k = t >> 7, o = t & 127;
            int ep = eb + o, h = ep >> 6, e = ep & 63;
            Ms[k][o] = g_M[h*4096 + (kt*32 + k)*64 + e];
        }
        for (int t = tid; t < 2048; t += 256) {
            int pp = t >> 5, k = t & 31;
            Qs[pp][k] = g_pts[(size_t)(p0 + pp)*64 + kt*32 + k];
        }
        __syncthreads();
        #pragma unroll 8
        for (int k = 0; k < 32; k++) {
            float a[4], bb[8];
            #pragma unroll
            for (int pp = 0; pp < 4; pp++) a[pp] = Qs[ty*4 + pp][k];
            *(float4*)bb     = *(float4*)&Ms[k][tx*8];
            *(float4*)(bb+4) = *(float4*)&Ms[k][tx*8 + 4];
            #pragma unroll
            for (int pp = 0; pp < 4; pp++)
                #pragma unroll
                for (int ee = 0; ee < 8; ee++)
                    acc[pp][ee] += a[pp] * bb[ee];
        }
        __syncthreads();
    }
    #pragma unroll
    for (int pp = 0; pp < 4; pp++) {
        size_t rb = (size_t)(p0 + ty*4 + pp)*256 + eb + tx*8;
        *(float4*)&g_tq[rb]     = make_float4(acc[pp][0], acc[pp][1], acc[pp][2], acc[pp][3]);
        *(float4*)&g_tq[rb + 4] = make_float4(acc[pp][4], acc[pp][5], acc[pp][6], acc[pp][7]);
    }
}

// ---------------- K: per-point attention -> weighted difference vectors ----------------
#define WPB 8
__global__ void k_attn() {
    __shared__ float nb[WPB][KNN][65];   // 65: bank-conflict-free rows
    __shared__ float tqs[WPB][64];
    __shared__ float ps[WPB][KNN];
    __shared__ int   nbi[WPB][KNN];

    int w = threadIdx.x >> 5;
    int lane = threadIdx.x & 31;
    int p = blockIdx.x * WPB + w;
    int b = p >> 12;

    if (lane < KNN) nbi[w][lane] = g_idx[p * KNN + lane];
    float q0 = g_pts[(size_t)p*64 + lane];
    float q1 = g_pts[(size_t)p*64 + 32 + lane];
    __syncwarp();
    #pragma unroll 4
    for (int k = 0; k < KNN; k++) {
        int j = nbi[w][k];
        const float* src = g_pts + ((size_t)(b << 12) + j)*64;
        nb[w][k][lane]      = src[lane];
        nb[w][k][lane + 32] = src[lane + 32];
    }
    __syncwarp();

    for (int h = 0; h < HH; h++) {
        tqs[w][lane]      = g_tq[(size_t)p*256 + h*64 + lane];
        tqs[w][lane + 32] = g_tq[(size_t)p*256 + h*64 + 32 + lane];
        __syncwarp();

        float s = -3.402823466e38f;
        if (lane < KNN) {
            float acc = 0.f;
            #pragma unroll 8
            for (int c = 0; c < 64; c++) acc += tqs[w][c] * nb[w][lane][c];
            s = acc * 0.125f;
        }
        float mx = s;
        #pragma unroll
        for (int off = 16; off; off >>= 1) mx = fmaxf(mx, __shfl_xor_sync(0xFFFFFFFFu, mx, off));
        float e = (lane < KNN) ? expf(s - mx) : 0.f;
        float sum = e;
        #pragma unroll
        for (int off = 16; off; off >>= 1) sum += __shfl_xor_sync(0xFFFFFFFFu, sum, off);
        if (lane < KNN) ps[w][lane] = e / sum;
        __syncwarp();

        float w0 = 0.f, w1 = 0.f;
        #pragma unroll 4
        for (int k = 0; k < KNN; k++) {
            float pk = ps[w][k];
            w0 += pk * (nb[w][k][lane]      - q0);
            w1 += pk * (nb[w][k][lane + 32] - q1);
        }
        g_wd[((size_t)p*HH + h)*64 + lane]      = w0;
        g_wd[((size_t)p*HH + h)*64 + 32 + lane] = w1;
        __syncwarp();
    }
}

// ---------------- K: y = Wf (128x256) @ wd^T ----------------
__global__ void k_ygemm() {
    __shared__ float Wfs[32][129];
    __shared__ float wds[64][33];
    int tid = threadIdx.y * 16 + threadIdx.x;
    int p0 = blockIdx.x * 64;
    float acc[8][4] = {};

    for (int kt = 0; kt < 8; kt++) {
        for (int t = tid; t < 4096; t += 256) {
            int o = t >> 5, k = t & 31;
            Wfs[k][o] = g_Wf[o*256 + kt*32 + k];
        }
        for (int t = tid; t < 2048; t += 256) {
            int pp = t >> 5, k = t & 31;
            wds[pp][k] = g_wd[(size_t)(p0 + pp)*256 + kt*32 + k];
        }
        __syncthreads();
        #pragma unroll 8
        for (int k = 0; k < 32; k++) {
            float a[8], bb[4];
            #pragma unroll
            for (int ii = 0; ii < 8; ii++) a[ii] = Wfs[k][threadIdx.y*8 + ii];
            #pragma unroll
            for (int jj = 0; jj < 4; jj++) bb[jj] = wds[threadIdx.x*4 + jj][k];
            #pragma unroll
            for (int ii = 0; ii < 8; ii++)
                #pragma unroll
                for (int jj = 0; jj < 4; jj++)
                    acc[ii][jj] += a[ii] * bb[jj];
        }
        __syncthreads();
    }
    #pragma unroll
    for (int ii = 0; ii < 8; ii++) {
        int o = threadIdx.y*8 + ii;
        #pragma unroll
        for (int jj = 0; jj < 4; jj++) {
            int p = p0 + threadIdx.x*4 + jj;
            g_y[((size_t)(p >> 12)*OO + o)*NN + (p & 4095)] = acc[ii][jj];
        }
    }
}

// ---------------- K: BN stats (double accumulation) ----------------
__global__ void k_bnstats() {
    __shared__ double rs[256], rss[256];
    int o = blockIdx.x;
    int tid = threadIdx.x;
    double s = 0.0, ss = 0.0;
    for (int b = 0; b < BB; b++) {
        const float* row = g_y + ((size_t)b*OO + o)*NN;
        for (int t = tid; t < NN; t += 256) {
            double v = (double)row[t];
            s += v; ss += v*v;
        }
    }
    rs[tid] = s; rss[tid] = ss;
    __syncthreads();
    for (int st = 128; st; st >>= 1) {
        if (tid < st) { rs[tid] += rs[tid + st]; rss[tid] += rss[tid + st]; }
        __syncthreads();
    }
    if (tid == 0) {
        double n = (double)(BB*NN);
        double mean = rs[0] / n;
        double var = rss[0] / n - mean*mean;
        g_mean[o] = (float)mean;
        g_istd[o] = (float)(1.0 / sqrt(var + 1e-5));
    }
}

// ---------------- K: BN apply + LeakyReLU -> out channels [0,128) ----------------
__global__ void k_bnapply(const float* __restrict__ gamma, const float* __restrict__ beta,
                          float* __restrict__ out) {
    size_t i = (size_t)blockIdx.x * blockDim.x + threadIdx.x;
    if (i >= (size_t)BB*OO*NN) return;
    int n = (int)(i & (NN-1));
    size_t t = i >> 12;
    int o = (int)(t & (OO-1));
    int b = (int)(t >> 7);
    float v = (g_y[i] - g_mean[o]) * g_istd[o] * gamma[o] + beta[o];
    v = (v >= 0.f) ? v : 0.2f * v;
    out[((size_t)b*192 + o)*NN + n] = v;
}

// ---------------- launch ----------------
extern "C" void kernel_launch(void* const* d_in, const int* in_sizes, int n_in,
                              void* d_out, int out_size) {
    const float* x     = (const float*)d_in[0];
    const float* Wq    = (const float*)d_in[1];
    const float* Wk    = (const float*)d_in[2];
    const float* Wv    = (const float*)d_in[3];
    const float* Wout  = (const float*)d_in[4];
    const float* gamma = (const float*)d_in[5];
    const float* beta  = (const float*)d_in[6];
    float* out = (float*)d_out;

    cudaFuncSetAttribute(k_pdist, cudaFuncAttributeMaxDynamicSharedMemorySize, PD_SMEM_BYTES);

    k_transpose<<<dim3(NN/32, CC/32, BB), dim3(32, 8)>>>(x);
    k_precWf<<<128, 256>>>(Wout, Wv);
    k_pdist<<<dim3(32, 32, BB), 256, PD_SMEM_BYTES>>>(x);
    k_topk<<<256, 256>>>();                                  // 4th launch -> profiled
    k_copyx<<<(BB*CC*NN)/256, 256>>>(x, out);
    k_precM<<<64, 256>>>(Wq, Wk);
    k_qt<<<dim3(PP/64, 2), dim3(16, 16)>>>();
    k_attn<<<PP/WPB, 256>>>();
    k_ygemm<<<PP/64, dim3(16, 16)>>>();
    k_bnstats<<<OO, 256>>>();
    k_bnapply<<<(BB*OO*NN)/256, 256>>>(gamma, beta, out);
}